// round 14
// baseline (speedup 1.0000x reference)
#include <cuda_runtime.h>
#include <cuda_fp16.h>
#include <cstdint>

// ---------------------------------------------------------------------------
// Problem dims (fixed by the dataset)
// ---------------------------------------------------------------------------
#define HDIM 4096
#define IDIM 14336
#define MDIM 4096   // BT * S = 2 * 2048
#define RNK  16

__constant__ float c_nf4[16] = {
  -1.0f, -0.6961928009986877f, -0.5250730514526367f, -0.39491748809814453f,
  -0.28444138169288635f, -0.18477343022823334f, -0.09105003625154495f, 0.0f,
  0.07958029955625534f, 0.16093020141124725f, 0.24611230194568634f,
  0.33791524171829224f, 0.44070982933044434f, 0.5626170039176941f,
  0.7229568362236023f, 1.0f};

// ---------------------------------------------------------------------------
// Scratch (static __device__ arrays: allocation-free per harness rules)
// ---------------------------------------------------------------------------
__device__ __half g_xh  [(size_t)MDIM * HDIM];
__device__ __half g_Wqkv[(size_t)HDIM * HDIM];
__device__ __half g_Wo  [(size_t)HDIM * HDIM];
__device__ __half g_Wgu [(size_t)2 * IDIM * HDIM];   // interleaved: row 2j=gate_j, 2j+1=up_j
__device__ __half g_Wd  [(size_t)HDIM * IDIM];
__device__ __half g_attn[(size_t)MDIM * HDIM];
__device__ __half g_x1h [(size_t)MDIM * HDIM];
__device__ float  g_x1f [(size_t)MDIM * HDIM];
__device__ __half g_hb  [(size_t)MDIM * IDIM];
__device__ float  g_part[(size_t)MDIM * HDIM];       // split-K partial for G4

// ---------------------------------------------------------------------------
// Dequant + LoRA-fold, QKV-fused (3 code planes summed, mul=1/3).
// 2 h per thread, rank-48 LoRA A in regs, depth-2 load rotation (MLP ~9).
// ---------------------------------------------------------------------------
__global__ void __launch_bounds__(256, 1)
dq3_kernel(const int* __restrict__ codes,
           const float* __restrict__ scales,
           const float* __restrict__ Amat,   // [48, K]
           const float* __restrict__ Bmat,   // [4, O, 16] planes
           __half* __restrict__ W,
           int O, int K,
           long codePlane, long scalePlane, long bPlane,
           float mul)
{
  constexpr int RR = 48;
  constexpr int OT = 32;
  __shared__ float sB[OT * RR];
  const int tid = threadIdx.x;         // 256 threads
  const int h0 = blockIdx.x * 512;
  const int o0 = blockIdx.y * OT;

  for (int i = tid; i < OT * RR; i += 256) {
    int oi = i / RR, r = i - oi * RR;
    sB[i] = Bmat[(long)(r >> 4) * bPlane + (long)(o0 + oi) * RNK + (r & 15)];
  }
  const int h = h0 + tid * 2;
  float2 areg[RR];
  #pragma unroll
  for (int r = 0; r < RR; ++r) {
    areg[r].x = Amat[(long)r * K + h] * mul;
    areg[r].y = Amat[(long)r * K + h + 1] * mul;
  }
  __syncthreads();

  const int hb = h >> 6;
  const int ks6 = K >> 6;

  int2  cbuf[2][3];
  float sbuf[2][3];
  #pragma unroll
  for (int j = 0; j < 2; ++j)
    #pragma unroll
    for (int p = 0; p < 3; ++p) {
      cbuf[j][p] = *(const int2*)(codes + p * codePlane + (long)(o0 + j) * K + h);
      sbuf[j][p] = scales[p * scalePlane + (long)(o0 + j) * ks6 + hb];
    }

  #pragma unroll 2
  for (int oi = 0; oi < OT; ++oi) {
    const int slot = oi & 1;
    int2  cc[3];
    float ss[3];
    #pragma unroll
    for (int p = 0; p < 3; ++p) { cc[p] = cbuf[slot][p]; ss[p] = sbuf[slot][p]; }
    if (oi + 2 < OT) {
      #pragma unroll
      for (int p = 0; p < 3; ++p) {
        cbuf[slot][p] = *(const int2*)(codes + p * codePlane + (long)(o0 + oi + 2) * K + h);
        sbuf[slot][p] = scales[p * scalePlane + (long)(o0 + oi + 2) * ks6 + hb];
      }
    }
    float v0 = 0.f, v1 = 0.f;
    #pragma unroll
    for (int p = 0; p < 3; ++p) {
      v0 += c_nf4[cc[p].x & 15] * ss[p];
      v1 += c_nf4[cc[p].y & 15] * ss[p];
    }
    v0 *= mul; v1 *= mul;
    #pragma unroll
    for (int r = 0; r < RR; ++r) {
      float b = sB[oi * RR + r];
      v0 += b * areg[r].x;
      v1 += b * areg[r].y;
    }
    __half2 pk = __floats2half2_rn(v0, v1);
    *(__half2*)(W + (long)(o0 + oi) * K + h) = pk;
  }
}

// ---------------------------------------------------------------------------
// Dequant + LoRA-fold, single plane, 4 h per thread, 4-deep load rotation.
// rowStride (elements) allows interleaved output rows (gu fusion).
// ---------------------------------------------------------------------------
__global__ void dq1_kernel(const int* __restrict__ codes,
                           const float* __restrict__ scales,
                           const float* __restrict__ Amat,   // [16, K]
                           const float* __restrict__ Bmat,   // [O, 16]
                           __half* __restrict__ W,
                           int O, int K, long rowStride)
{
  constexpr int RR = 16;
  constexpr int OT = 32;
  __shared__ float sB[OT * RR];
  const int tid = threadIdx.x;         // 256 threads
  const int h0 = blockIdx.x * 1024;
  const int o0 = blockIdx.y * OT;

  for (int i = tid; i < OT * RR; i += 256) {
    int oi = i / RR, r = i - oi * RR;
    sB[i] = Bmat[(long)(o0 + oi) * RNK + r];
  }
  const int h = h0 + tid * 4;
  float4 areg[RR];
  #pragma unroll
  for (int r = 0; r < RR; ++r)
    areg[r] = *(const float4*)(Amat + (long)r * K + h);
  __syncthreads();

  const int hb = h >> 6;
  const int ks6 = K >> 6;

  int4  c[4];
  float s[4];
  #pragma unroll
  for (int j = 0; j < 4; ++j) {
    c[j] = *(const int4*)(codes + (long)(o0 + j) * K + h);
    s[j] = scales[(long)(o0 + j) * ks6 + hb];
  }

  #pragma unroll 4
  for (int oi = 0; oi < OT; ++oi) {
    const int slot = oi & 3;
    int4  cc = c[slot];
    float ss = s[slot];
    if (oi + 4 < OT) {
      c[slot] = *(const int4*)(codes + (long)(o0 + oi + 4) * K + h);
      s[slot] = scales[(long)(o0 + oi + 4) * ks6 + hb];
    }
    float v0 = c_nf4[cc.x & 15] * ss;
    float v1 = c_nf4[cc.y & 15] * ss;
    float v2 = c_nf4[cc.z & 15] * ss;
    float v3 = c_nf4[cc.w & 15] * ss;
    #pragma unroll
    for (int r = 0; r < RR; ++r) {
      float b = sB[oi * RR + r];
      v0 += b * areg[r].x;
      v1 += b * areg[r].y;
      v2 += b * areg[r].z;
      v3 += b * areg[r].w;
    }
    __half2 lo = __floats2half2_rn(v0, v1);
    __half2 hi = __floats2half2_rn(v2, v3);
    uint2 pk;
    pk.x = *(uint32_t*)&lo;
    pk.y = *(uint32_t*)&hi;
    *(uint2*)(W + (long)(o0 + oi) * rowStride + h) = pk;
  }
}

// ---------------------------------------------------------------------------
// fp16 GEMM:  C[M,N] = A[M,K] @ B[N,K]^T, fp32 accum.
// Tile 128x256x64, 8 warps (2x4), warp tile 64x64, mma.sync.m16n8k16.
// 4-stage cp.async pipeline; double-buffered LDSM frags; spread prefetch.
// Klen = K-range per CTA (split-K via blockIdx.z; Kdim remains row stride).
// EPI: 0 half(C); 1 f=resid+C f32+half; 3 silu(g)*u->half; 4 f32 (OF/OF2 by z).
// ---------------------------------------------------------------------------
#define BM 128
#define BN 256
#define BK 64
#define STG 4
#define STAGE_B ((BM + BN) * BK * 2)          // 49152
#define SMEM_GEMM (STG * STAGE_B)             // 196608

__device__ __forceinline__ void cp16(uint32_t dst, const void* src) {
  asm volatile("cp.async.cg.shared.global [%0], [%1], 16;" :: "r"(dst), "l"(src));
}

__device__ __forceinline__ void gemm_load_stage(const __half* __restrict__ Ag,
                                                const __half* __restrict__ Bg,
                                                long Kdim, int m0, int n0,
                                                int lrow, int lcc, uint32_t off0,
                                                uint32_t sbase, int st, int kt)
{
  const long k0 = (long)kt * BK;
  uint32_t sA = sbase + (uint32_t)st * STAGE_B;
  uint32_t sB = sA + BM * BK * 2u;
  const __half* gA = Ag + (long)(m0 + lrow) * Kdim + k0 + lcc * 8;
  const __half* gB = Bg + (long)(n0 + lrow) * Kdim + k0 + lcc * 8;
  #pragma unroll
  for (int i = 0; i < 4; ++i)
    cp16(sA + off0 + (uint32_t)i * 4096u, gA + (long)i * 32 * Kdim);
  #pragma unroll
  for (int i = 0; i < 8; ++i)
    cp16(sB + off0 + (uint32_t)i * 4096u, gB + (long)i * 32 * Kdim);
  asm volatile("cp.async.commit_group;");
}

__device__ __forceinline__ void ld_frags(uint32_t sA, uint32_t sB,
                                         int wm, int wn, int lane, int ks,
                                         uint32_t af[4][4], uint32_t bf[8][2])
{
  #pragma unroll
  for (int mi = 0; mi < 4; ++mi) {
    int row = wm * 64 + mi * 16 + (lane & 15);
    int c3  = 2 * ks + (lane >> 4);
    uint32_t addr = sA + (uint32_t)row * 128u +
                    ((uint32_t)((c3 ^ (row & 7))) << 4);
    asm volatile("ldmatrix.sync.aligned.m8n8.x4.shared.b16 {%0,%1,%2,%3}, [%4];"
                 : "=r"(af[mi][0]), "=r"(af[mi][1]), "=r"(af[mi][2]), "=r"(af[mi][3])
                 : "r"(addr));
  }
  #pragma unroll
  for (int nb = 0; nb < 4; ++nb) {
    int row = wn * 64 + nb * 16 + (lane & 7) + ((lane >> 4) << 3);
    int c3  = 2 * ks + ((lane >> 3) & 1);
    uint32_t addr = sB + (uint32_t)row * 128u +
                    ((uint32_t)((c3 ^ (row & 7))) << 4);
    asm volatile("ldmatrix.sync.aligned.m8n8.x4.shared.b16 {%0,%1,%2,%3}, [%4];"
                 : "=r"(bf[2*nb][0]), "=r"(bf[2*nb][1]),
                   "=r"(bf[2*nb+1][0]), "=r"(bf[2*nb+1][1])
                 : "r"(addr));
  }
}

template<int EPI>
__global__ void __launch_bounds__(256, 1)
gemm_kernel(const __half* __restrict__ Ag, const __half* __restrict__ Bg,
            const float* __restrict__ Rg, __half* __restrict__ OH,
            float* __restrict__ OF, float* __restrict__ OF2,
            int Ndim, int Kdim, int Klen)
{
  extern __shared__ __half smem[];
  const int tid  = threadIdx.x;
  const int m0   = blockIdx.x * BM;   // m fastest -> W n-band reused across wave
  const int n0   = blockIdx.y * BN;
  const long koff = (long)blockIdx.z * Klen;
  Ag += koff;  Bg += koff;
  if (EPI == 4 && blockIdx.z) OF = OF2;
  const uint32_t sbase = (uint32_t)__cvta_generic_to_shared(smem);
  const int warp = tid >> 5, lane = tid & 31;
  const int wm = warp & 1, wn = warp >> 1;          // 2 x 4 warps
  const int lrow = tid >> 3, lcc = tid & 7;
  const uint32_t off0 = (uint32_t)lrow * 128u +
                        ((uint32_t)(lcc ^ (lrow & 7)) << 4);
  const int KT = Klen / BK;

  float acc[4][8][4];
  #pragma unroll
  for (int a = 0; a < 4; ++a)
    #pragma unroll
    for (int b = 0; b < 8; ++b)
      #pragma unroll
      for (int c = 0; c < 4; ++c) acc[a][b][c] = 0.f;

  gemm_load_stage(Ag, Bg, Kdim, m0, n0, lrow, lcc, off0, sbase, 0, 0);
  gemm_load_stage(Ag, Bg, Kdim, m0, n0, lrow, lcc, off0, sbase, 1, 1);
  gemm_load_stage(Ag, Bg, Kdim, m0, n0, lrow, lcc, off0, sbase, 2, 2);

  uint32_t af[2][4][4], bf[2][8][2];

  for (int kt = 0; kt < KT; ++kt) {
    asm volatile("cp.async.wait_group 2;");
    __syncthreads();

    uint32_t sA = sbase + (uint32_t)(kt & 3) * STAGE_B;
    uint32_t sB = sA + BM * BK * 2u;

    // Next-stage (kt+3); its buffer (kt-1)&3 was fully consumed in iter kt-1.
    const bool pf = (kt + 3 < KT);
    const long pk0 = (long)(kt + 3) * BK;
    uint32_t pA = sbase + (uint32_t)((kt + 3) & 3) * STAGE_B;
    uint32_t pB = pA + BM * BK * 2u;
    const __half* gA = Ag + (long)(m0 + lrow) * Kdim + pk0 + lcc * 8;
    const __half* gB = Bg + (long)(n0 + lrow) * Kdim + pk0 + lcc * 8;

    ld_frags(sA, sB, wm, wn, lane, 0, af[0], bf[0]);

    #pragma unroll
    for (int ks = 0; ks < 4; ++ks) {
      if (ks < 3)
        ld_frags(sA, sB, wm, wn, lane, ks + 1, af[(ks + 1) & 1], bf[(ks + 1) & 1]);
      if (ks == 0 && pf) {
        #pragma unroll
        for (int i = 0; i < 4; ++i)
          cp16(pA + off0 + (uint32_t)i * 4096u, gA + (long)i * 32 * Kdim);
      }
      if (ks == 1 && pf) {
        #pragma unroll
        for (int i = 0; i < 4; ++i)
          cp16(pB + off0 + (uint32_t)i * 4096u, gB + (long)i * 32 * Kdim);
      }
      if (ks == 2 && pf) {
        #pragma unroll
        for (int i = 4; i < 8; ++i)
          cp16(pB + off0 + (uint32_t)i * 4096u, gB + (long)i * 32 * Kdim);
      }
      if (ks == 3)
        asm volatile("cp.async.commit_group;");   // empty group at tail keeps count

      const int cb = ks & 1;
      #pragma unroll
      for (int mi = 0; mi < 4; ++mi)
        #pragma unroll
        for (int ni = 0; ni < 8; ++ni)
          asm volatile("mma.sync.aligned.m16n8k16.row.col.f32.f16.f16.f32 "
                       "{%0,%1,%2,%3}, {%4,%5,%6,%7}, {%8,%9}, {%0,%1,%2,%3};"
                       : "+f"(acc[mi][ni][0]), "+f"(acc[mi][ni][1]),
                         "+f"(acc[mi][ni][2]), "+f"(acc[mi][ni][3])
                       : "r"(af[cb][mi][0]), "r"(af[cb][mi][1]),
                         "r"(af[cb][mi][2]), "r"(af[cb][mi][3]),
                         "r"(bf[cb][ni][0]), "r"(bf[cb][ni][1]));
    }
  }

  // Epilogue (registers only)
  if (EPI == 3) {
    // interleaved [g|u] columns: even col = gate, odd col = up (same j)
    const long mb2 = m0 + wm * 64 + (lane >> 2);
    const int  jb  = ((n0 + wn * 64) >> 1) + (lane & 3);
    #pragma unroll
    for (int mi = 0; mi < 4; ++mi) {
      #pragma unroll
      for (int ni = 0; ni < 8; ++ni) {
        long r = mb2 + mi * 16;
        int  j = jb + ni * 4;
        float ga = acc[mi][ni][0], ua = acc[mi][ni][1];
        float gb2 = acc[mi][ni][2], ub = acc[mi][ni][3];
        float ha = ga / (1.f + __expf(-ga)) * ua;
        float hbv = gb2 / (1.f + __expf(-gb2)) * ub;
        OH[r * (long)Ndim + j]       = __float2half(ha);
        OH[(r + 8) * (long)Ndim + j] = __float2half(hbv);
      }
    }
    return;
  }
  const long mbase = m0 + wm * 64 + (lane >> 2);
  const long nbase = n0 + wn * 64 + (lane & 3) * 2;
  #pragma unroll
  for (int mi = 0; mi < 4; ++mi) {
    #pragma unroll
    for (int ni = 0; ni < 8; ++ni) {
      long r = mbase + mi * 16;
      long c = nbase + ni * 8;
      long i0 = r * Ndim + c;
      long i1 = (r + 8) * Ndim + c;
      float v0 = acc[mi][ni][0], v1 = acc[mi][ni][1];
      float v2 = acc[mi][ni][2], v3 = acc[mi][ni][3];
      if (EPI == 4) {
        *(float2*)(OF + i0) = make_float2(v0, v1);
        *(float2*)(OF + i1) = make_float2(v2, v3);
      } else {
        if (EPI >= 1) {
          float2 ra = *(const float2*)(Rg + i0);
          float2 rb = *(const float2*)(Rg + i1);
          v0 += ra.x; v1 += ra.y; v2 += rb.x; v3 += rb.y;
          *(float2*)(OF + i0) = make_float2(v0, v1);
          *(float2*)(OF + i1) = make_float2(v2, v3);
        }
        if (EPI <= 1) {
          *(__half2*)(OH + i0) = __floats2half2_rn(v0, v1);
          *(__half2*)(OH + i1) = __floats2half2_rn(v2, v3);
        }
      }
    }
  }
}

// ---------------------------------------------------------------------------
// Elementwise
// ---------------------------------------------------------------------------
__global__ void cvt_kernel(const float* __restrict__ x, __half* __restrict__ y) {
  long i = ((long)blockIdx.x * 256 + threadIdx.x) * 4;
  float4 v = *(const float4*)(x + i);
  __half2 lo = __floats2half2_rn(v.x, v.y);
  __half2 hi = __floats2half2_rn(v.z, v.w);
  uint2 pk;
  pk.x = *(uint32_t*)&lo;
  pk.y = *(uint32_t*)&hi;
  *(uint2*)(y + i) = pk;
}

// out = x1f + part0 + out(=part1), vectorized float4
__global__ void reduce_kernel(const float* __restrict__ x1f,
                              const float* __restrict__ part,
                              float* __restrict__ out) {
  long i = ((long)blockIdx.x * 256 + threadIdx.x) * 4;
  float4 a = *(const float4*)(x1f + i);
  float4 b = *(const float4*)(part + i);
  float4 c = *(const float4*)(out + i);
  c.x += a.x + b.x;  c.y += a.y + b.y;
  c.z += a.z + b.z;  c.w += a.w + b.w;
  *(float4*)(out + i) = c;
}

// ---------------------------------------------------------------------------
// Host driver (graph-capturable; three streams forked/joined with events)
// ---------------------------------------------------------------------------
extern "C" void kernel_launch(void* const* d_in, const int* in_sizes, int n_in,
                              void* d_out, int out_size) {
  const float* x           = (const float*)d_in[0];
  const int*   codes_attn  = (const int*)  d_in[1];
  const float* scales_attn = (const float*)d_in[2];
  const int*   codes_gu    = (const int*)  d_in[3];
  const float* scales_gu   = (const float*)d_in[4];
  const int*   codes_down  = (const int*)  d_in[5];
  const float* scales_down = (const float*)d_in[6];
  const float* lora_A_h    = (const float*)d_in[7];
  const float* lora_A_down = (const float*)d_in[8];
  const float* lora_B_attn = (const float*)d_in[9];
  const float* lora_B_gu   = (const float*)d_in[10];
  const float* lora_B_down = (const float*)d_in[11];
  (void)in_sizes; (void)n_in; (void)out_size;

  __half *xh, *Wqkv, *Wo, *Wgu, *Wd, *attn, *x1h, *hb;
  float *x1f, *part;
  cudaGetSymbolAddress((void**)&xh,   g_xh);
  cudaGetSymbolAddress((void**)&Wqkv, g_Wqkv);
  cudaGetSymbolAddress((void**)&Wo,   g_Wo);
  cudaGetSymbolAddress((void**)&Wgu,  g_Wgu);
  cudaGetSymbolAddress((void**)&Wd,   g_Wd);
  cudaGetSymbolAddress((void**)&attn, g_attn);
  cudaGetSymbolAddress((void**)&x1h,  g_x1h);
  cudaGetSymbolAddress((void**)&x1f,  g_x1f);
  cudaGetSymbolAddress((void**)&hb,   g_hb);
  cudaGetSymbolAddress((void**)&part, g_part);

  cudaFuncSetAttribute(gemm_kernel<0>, cudaFuncAttributeMaxDynamicSharedMemorySize, SMEM_GEMM);
  cudaFuncSetAttribute(gemm_kernel<1>, cudaFuncAttributeMaxDynamicSharedMemorySize, SMEM_GEMM);
  cudaFuncSetAttribute(gemm_kernel<3>, cudaFuncAttributeMaxDynamicSharedMemorySize, SMEM_GEMM);
  cudaFuncSetAttribute(gemm_kernel<4>, cudaFuncAttributeMaxDynamicSharedMemorySize, SMEM_GEMM);

  // One-time side streams + events (created on first (correctness) call,
  // outside graph capture; reused deterministically every call).
  static cudaStream_t s1 = nullptr, s2 = nullptr;
  static cudaEvent_t evFork = nullptr, evDq3 = nullptr, evDq1 = nullptr;
  if (s1 == nullptr) {
    cudaStreamCreateWithFlags(&s1, cudaStreamNonBlocking);
    cudaStreamCreateWithFlags(&s2, cudaStreamNonBlocking);
    cudaEventCreateWithFlags(&evFork, cudaEventDisableTiming);
    cudaEventCreateWithFlags(&evDq3,  cudaEventDisableTiming);
    cudaEventCreateWithFlags(&evDq1,  cudaEventDisableTiming);
  }

  // ---- fork ------------------------------------------------------------
  cudaEventRecord(evFork, 0);
  cudaStreamWaitEvent(s1, evFork, 0);
  cudaStreamWaitEvent(s2, evFork, 0);

  // s1: qkv-fused dequant (needed by GEMM1)
  dq3_kernel<<<dim3(HDIM / 512, HDIM / 32), 256, 0, s1>>>(
      codes_attn, scales_attn, lora_A_h, lora_B_attn, Wqkv, HDIM, HDIM,
      (long)HDIM * HDIM, (long)HDIM * (HDIM / 64), (long)HDIM * RNK, 1.f / 3.f);
  cudaEventRecord(evDq3, s1);

  // s2: remaining weight dequants (needed from GEMM2 on)
  dq1_kernel<<<dim3(HDIM / 1024, HDIM / 32), 256, 0, s2>>>(
      codes_attn + 3L * HDIM * HDIM, scales_attn + 3L * HDIM * (HDIM / 64),
      lora_A_h + 3L * RNK * HDIM, lora_B_attn + 3L * HDIM * RNK,
      Wo, HDIM, HDIM, HDIM);
  dq1_kernel<<<dim3(HDIM / 1024, IDIM / 32), 256, 0, s2>>>(
      codes_gu, scales_gu, lora_A_h + 4L * RNK * HDIM, lora_B_gu,
      Wgu, IDIM, HDIM, 2L * HDIM);                       // gate -> rows 2j
  dq1_kernel<<<dim3(HDIM / 1024, IDIM / 32), 256, 0, s2>>>(
      codes_gu + (long)IDIM * HDIM, scales_gu + (long)IDIM * (HDIM / 64),
      lora_A_h + 5L * RNK * HDIM, lora_B_gu + (long)IDIM * RNK,
      Wgu + HDIM, IDIM, HDIM, 2L * HDIM);                // up -> rows 2j+1
  dq1_kernel<<<dim3(IDIM / 1024, HDIM / 32), 256, 0, s2>>>(
      codes_down, scales_down, lora_A_down, lora_B_down,
      Wd, HDIM, IDIM, IDIM);
  cudaEventRecord(evDq1, s2);

  // ---- main stream: x -> fp16, then GEMM chain -------------------------
  cvt_kernel<<<(MDIM * (long)HDIM) / 1024, 256>>>(x, xh);

  cudaStreamWaitEvent(0, evDq3, 0);
  // attn = xh @ Wqkv^T   (already = (q+k+v)/3)
  gemm_kernel<0><<<dim3(MDIM / BM, HDIM / BN), 256, SMEM_GEMM>>>(
      xh, Wqkv, nullptr, attn, nullptr, nullptr, HDIM, HDIM, HDIM);

  cudaStreamWaitEvent(0, evDq1, 0);
  // x1 = x + attn @ Wo^T  (store fp32 + fp16)
  gemm_kernel<1><<<dim3(MDIM / BM, HDIM / BN), 256, SMEM_GEMM>>>(
      attn, Wo, x, x1h, x1f, nullptr, HDIM, HDIM, HDIM);
  // hb = silu(g) * u  fused into the gu GEMM (interleaved Wgu)
  gemm_kernel<3><<<dim3(MDIM / BM, (2 * IDIM) / BN), 256, SMEM_GEMM>>>(
      x1h, Wgu, nullptr, hb, nullptr, nullptr, IDIM, HDIM, HDIM);
  // split-K=2:  z=0 -> part, z=1 -> d_out  (each half K = 7168)
  gemm_kernel<4><<<dim3(MDIM / BM, HDIM / BN, 2), 256, SMEM_GEMM>>>(
      hb, Wd, nullptr, nullptr, part, (float*)d_out, HDIM, IDIM, IDIM / 2);
  // out = x1 + part0 + part1
  reduce_kernel<<<(MDIM * (long)HDIM) / 1024, 256>>>(x1f, part, (float*)d_out);
}

// round 15
// speedup vs baseline: 1.0874x; 1.0874x over previous
#include <cuda_runtime.h>
#include <cuda_fp16.h>
#include <cstdint>

// ---------------------------------------------------------------------------
// Problem dims (fixed by the dataset)
// ---------------------------------------------------------------------------
#define HDIM 4096
#define IDIM 14336
#define MDIM 4096   // BT * S = 2 * 2048
#define RNK  16

__constant__ float c_nf4[16] = {
  -1.0f, -0.6961928009986877f, -0.5250730514526367f, -0.39491748809814453f,
  -0.28444138169288635f, -0.18477343022823334f, -0.09105003625154495f, 0.0f,
  0.07958029955625534f, 0.16093020141124725f, 0.24611230194568634f,
  0.33791524171829224f, 0.44070982933044434f, 0.5626170039176941f,
  0.7229568362236023f, 1.0f};

// ---------------------------------------------------------------------------
// Scratch (static __device__ arrays: allocation-free per harness rules)
// ---------------------------------------------------------------------------
__device__ __half g_xh  [(size_t)MDIM * HDIM];
__device__ __half g_Wqkv[(size_t)HDIM * HDIM];
__device__ __half g_Wo  [(size_t)HDIM * HDIM];
__device__ __half g_Wgu [(size_t)2 * IDIM * HDIM];   // interleaved: row 2j=gate_j, 2j+1=up_j
__device__ __half g_Wd  [(size_t)HDIM * IDIM];
__device__ __half g_attn[(size_t)MDIM * HDIM];
__device__ __half g_x1h [(size_t)MDIM * HDIM];
__device__ float  g_x1f [(size_t)MDIM * HDIM];
__device__ __half g_hb  [(size_t)MDIM * IDIM];

// ---------------------------------------------------------------------------
// Dequant + LoRA-fold, QKV-fused (3 code planes summed, mul=1/3).
// 2 h per thread, rank-48 LoRA A in regs, depth-2 load rotation.
// ---------------------------------------------------------------------------
__global__ void __launch_bounds__(256, 1)
dq3_kernel(const int* __restrict__ codes,
           const float* __restrict__ scales,
           const float* __restrict__ Amat,   // [48, K]
           const float* __restrict__ Bmat,   // [4, O, 16] planes
           __half* __restrict__ W,
           int O, int K,
           long codePlane, long scalePlane, long bPlane,
           float mul)
{
  constexpr int RR = 48;
  constexpr int OT = 32;
  __shared__ float sB[OT * RR];
  const int tid = threadIdx.x;         // 256 threads
  const int h0 = blockIdx.x * 512;
  const int o0 = blockIdx.y * OT;

  for (int i = tid; i < OT * RR; i += 256) {
    int oi = i / RR, r = i - oi * RR;
    sB[i] = Bmat[(long)(r >> 4) * bPlane + (long)(o0 + oi) * RNK + (r & 15)];
  }
  const int h = h0 + tid * 2;
  float2 areg[RR];
  #pragma unroll
  for (int r = 0; r < RR; ++r) {
    areg[r].x = Amat[(long)r * K + h] * mul;
    areg[r].y = Amat[(long)r * K + h + 1] * mul;
  }
  __syncthreads();

  const int hb = h >> 6;
  const int ks6 = K >> 6;

  int2  cbuf[2][3];
  float sbuf[2][3];
  #pragma unroll
  for (int j = 0; j < 2; ++j)
    #pragma unroll
    for (int p = 0; p < 3; ++p) {
      cbuf[j][p] = *(const int2*)(codes + p * codePlane + (long)(o0 + j) * K + h);
      sbuf[j][p] = scales[p * scalePlane + (long)(o0 + j) * ks6 + hb];
    }

  #pragma unroll 2
  for (int oi = 0; oi < OT; ++oi) {
    const int slot = oi & 1;
    int2  cc[3];
    float ss[3];
    #pragma unroll
    for (int p = 0; p < 3; ++p) { cc[p] = cbuf[slot][p]; ss[p] = sbuf[slot][p]; }
    if (oi + 2 < OT) {
      #pragma unroll
      for (int p = 0; p < 3; ++p) {
        cbuf[slot][p] = *(const int2*)(codes + p * codePlane + (long)(o0 + oi + 2) * K + h);
        sbuf[slot][p] = scales[p * scalePlane + (long)(o0 + oi + 2) * ks6 + hb];
      }
    }
    float v0 = 0.f, v1 = 0.f;
    #pragma unroll
    for (int p = 0; p < 3; ++p) {
      v0 += c_nf4[cc[p].x & 15] * ss[p];
      v1 += c_nf4[cc[p].y & 15] * ss[p];
    }
    v0 *= mul; v1 *= mul;
    #pragma unroll
    for (int r = 0; r < RR; ++r) {
      float b = sB[oi * RR + r];
      v0 += b * areg[r].x;
      v1 += b * areg[r].y;
    }
    __half2 pk = __floats2half2_rn(v0, v1);
    *(__half2*)(W + (long)(o0 + oi) * K + h) = pk;
  }
}

// ---------------------------------------------------------------------------
// Dequant + LoRA-fold, single plane, 4 h per thread, 4-deep load rotation.
// rowStride (elements) allows interleaved output rows (gu fusion).
// ---------------------------------------------------------------------------
__global__ void dq1_kernel(const int* __restrict__ codes,
                           const float* __restrict__ scales,
                           const float* __restrict__ Amat,   // [16, K]
                           const float* __restrict__ Bmat,   // [O, 16]
                           __half* __restrict__ W,
                           int O, int K, long rowStride)
{
  constexpr int RR = 16;
  constexpr int OT = 32;
  __shared__ float sB[OT * RR];
  const int tid = threadIdx.x;         // 256 threads
  const int h0 = blockIdx.x * 1024;
  const int o0 = blockIdx.y * OT;

  for (int i = tid; i < OT * RR; i += 256) {
    int oi = i / RR, r = i - oi * RR;
    sB[i] = Bmat[(long)(o0 + oi) * RNK + r];
  }
  const int h = h0 + tid * 4;
  float4 areg[RR];
  #pragma unroll
  for (int r = 0; r < RR; ++r)
    areg[r] = *(const float4*)(Amat + (long)r * K + h);
  __syncthreads();

  const int hb = h >> 6;
  const int ks6 = K >> 6;

  int4  c[4];
  float s[4];
  #pragma unroll
  for (int j = 0; j < 4; ++j) {
    c[j] = *(const int4*)(codes + (long)(o0 + j) * K + h);
    s[j] = scales[(long)(o0 + j) * ks6 + hb];
  }

  #pragma unroll 4
  for (int oi = 0; oi < OT; ++oi) {
    const int slot = oi & 3;
    int4  cc = c[slot];
    float ss = s[slot];
    if (oi + 4 < OT) {
      c[slot] = *(const int4*)(codes + (long)(o0 + oi + 4) * K + h);
      s[slot] = scales[(long)(o0 + oi + 4) * ks6 + hb];
    }
    float v0 = c_nf4[cc.x & 15] * ss;
    float v1 = c_nf4[cc.y & 15] * ss;
    float v2 = c_nf4[cc.z & 15] * ss;
    float v3 = c_nf4[cc.w & 15] * ss;
    #pragma unroll
    for (int r = 0; r < RR; ++r) {
      float b = sB[oi * RR + r];
      v0 += b * areg[r].x;
      v1 += b * areg[r].y;
      v2 += b * areg[r].z;
      v3 += b * areg[r].w;
    }
    __half2 lo = __floats2half2_rn(v0, v1);
    __half2 hi = __floats2half2_rn(v2, v3);
    uint2 pk;
    pk.x = *(uint32_t*)&lo;
    pk.y = *(uint32_t*)&hi;
    *(uint2*)(W + (long)(o0 + oi) * rowStride + h) = pk;
  }
}

// ---------------------------------------------------------------------------
// fp16 GEMM:  C[M,N] = A[M,K] @ B[N,K]^T, fp32 accum.
// Tile 128x256x64, 8 warps (2x4), warp tile 64x64, mma.sync.m16n8k16.
// 4-stage cp.async pipeline; double-buffered LDSM frags; spread prefetch.
// EPI: 0 half(C); 1 f=resid+C f32+half; 2 f32 only; 3 silu(g)*u -> half (gu).
// ---------------------------------------------------------------------------
#define BM 128
#define BN 256
#define BK 64
#define STG 4
#define STAGE_B ((BM + BN) * BK * 2)          // 49152
#define SMEM_GEMM (STG * STAGE_B)             // 196608

__device__ __forceinline__ void cp16(uint32_t dst, const void* src) {
  asm volatile("cp.async.cg.shared.global [%0], [%1], 16;" :: "r"(dst), "l"(src));
}

__device__ __forceinline__ void gemm_load_stage(const __half* __restrict__ Ag,
                                                const __half* __restrict__ Bg,
                                                long Kdim, int m0, int n0,
                                                int lrow, int lcc, uint32_t off0,
                                                uint32_t sbase, int st, int kt)
{
  const long k0 = (long)kt * BK;
  uint32_t sA = sbase + (uint32_t)st * STAGE_B;
  uint32_t sB = sA + BM * BK * 2u;
  const __half* gA = Ag + (long)(m0 + lrow) * Kdim + k0 + lcc * 8;
  const __half* gB = Bg + (long)(n0 + lrow) * Kdim + k0 + lcc * 8;
  #pragma unroll
  for (int i = 0; i < 4; ++i)
    cp16(sA + off0 + (uint32_t)i * 4096u, gA + (long)i * 32 * Kdim);
  #pragma unroll
  for (int i = 0; i < 8; ++i)
    cp16(sB + off0 + (uint32_t)i * 4096u, gB + (long)i * 32 * Kdim);
  asm volatile("cp.async.commit_group;");
}

__device__ __forceinline__ void ld_frags(uint32_t sA, uint32_t sB,
                                         int wm, int wn, int lane, int ks,
                                         uint32_t af[4][4], uint32_t bf[8][2])
{
  #pragma unroll
  for (int mi = 0; mi < 4; ++mi) {
    int row = wm * 64 + mi * 16 + (lane & 15);
    int c3  = 2 * ks + (lane >> 4);
    uint32_t addr = sA + (uint32_t)row * 128u +
                    ((uint32_t)((c3 ^ (row & 7))) << 4);
    asm volatile("ldmatrix.sync.aligned.m8n8.x4.shared.b16 {%0,%1,%2,%3}, [%4];"
                 : "=r"(af[mi][0]), "=r"(af[mi][1]), "=r"(af[mi][2]), "=r"(af[mi][3])
                 : "r"(addr));
  }
  #pragma unroll
  for (int nb = 0; nb < 4; ++nb) {
    int row = wn * 64 + nb * 16 + (lane & 7) + ((lane >> 4) << 3);
    int c3  = 2 * ks + ((lane >> 3) & 1);
    uint32_t addr = sB + (uint32_t)row * 128u +
                    ((uint32_t)((c3 ^ (row & 7))) << 4);
    asm volatile("ldmatrix.sync.aligned.m8n8.x4.shared.b16 {%0,%1,%2,%3}, [%4];"
                 : "=r"(bf[2*nb][0]), "=r"(bf[2*nb][1]),
                   "=r"(bf[2*nb+1][0]), "=r"(bf[2*nb+1][1])
                 : "r"(addr));
  }
}

template<int EPI>
__global__ void __launch_bounds__(256, 1)
gemm_kernel(const __half* __restrict__ Ag, const __half* __restrict__ Bg,
            const float* __restrict__ Rg, __half* __restrict__ OH,
            float* __restrict__ OF, int Ndim, int Kdim)
{
  extern __shared__ __half smem[];
  const int tid  = threadIdx.x;
  const int m0   = blockIdx.x * BM;   // m fastest -> W n-band reused across wave
  const int n0   = blockIdx.y * BN;
  const uint32_t sbase = (uint32_t)__cvta_generic_to_shared(smem);
  const int warp = tid >> 5, lane = tid & 31;
  const int wm = warp & 1, wn = warp >> 1;          // 2 x 4 warps
  const int lrow = tid >> 3, lcc = tid & 7;
  const uint32_t off0 = (uint32_t)lrow * 128u +
                        ((uint32_t)(lcc ^ (lrow & 7)) << 4);
  const int KT = Kdim / BK;

  float acc[4][8][4];
  #pragma unroll
  for (int a = 0; a < 4; ++a)
    #pragma unroll
    for (int b = 0; b < 8; ++b)
      #pragma unroll
      for (int c = 0; c < 4; ++c) acc[a][b][c] = 0.f;

  gemm_load_stage(Ag, Bg, Kdim, m0, n0, lrow, lcc, off0, sbase, 0, 0);
  gemm_load_stage(Ag, Bg, Kdim, m0, n0, lrow, lcc, off0, sbase, 1, 1);
  gemm_load_stage(Ag, Bg, Kdim, m0, n0, lrow, lcc, off0, sbase, 2, 2);

  uint32_t af[2][4][4], bf[2][8][2];

  for (int kt = 0; kt < KT; ++kt) {
    asm volatile("cp.async.wait_group 2;");
    __syncthreads();

    uint32_t sA = sbase + (uint32_t)(kt & 3) * STAGE_B;
    uint32_t sB = sA + BM * BK * 2u;

    // Next-stage (kt+3); its buffer (kt-1)&3 was fully consumed in iter kt-1.
    const bool pf = (kt + 3 < KT);
    const long pk0 = (long)(kt + 3) * BK;
    uint32_t pA = sbase + (uint32_t)((kt + 3) & 3) * STAGE_B;
    uint32_t pB = pA + BM * BK * 2u;
    const __half* gA = Ag + (long)(m0 + lrow) * Kdim + pk0 + lcc * 8;
    const __half* gB = Bg + (long)(n0 + lrow) * Kdim + pk0 + lcc * 8;

    ld_frags(sA, sB, wm, wn, lane, 0, af[0], bf[0]);

    #pragma unroll
    for (int ks = 0; ks < 4; ++ks) {
      if (ks < 3)
        ld_frags(sA, sB, wm, wn, lane, ks + 1, af[(ks + 1) & 1], bf[(ks + 1) & 1]);
      if (ks == 0 && pf) {
        #pragma unroll
        for (int i = 0; i < 4; ++i)
          cp16(pA + off0 + (uint32_t)i * 4096u, gA + (long)i * 32 * Kdim);
      }
      if (ks == 1 && pf) {
        #pragma unroll
        for (int i = 0; i < 4; ++i)
          cp16(pB + off0 + (uint32_t)i * 4096u, gB + (long)i * 32 * Kdim);
      }
      if (ks == 2 && pf) {
        #pragma unroll
        for (int i = 4; i < 8; ++i)
          cp16(pB + off0 + (uint32_t)i * 4096u, gB + (long)i * 32 * Kdim);
      }
      if (ks == 3)
        asm volatile("cp.async.commit_group;");   // empty group at tail keeps count

      const int cb = ks & 1;
      #pragma unroll
      for (int mi = 0; mi < 4; ++mi)
        #pragma unroll
        for (int ni = 0; ni < 8; ++ni)
          asm volatile("mma.sync.aligned.m16n8k16.row.col.f32.f16.f16.f32 "
                       "{%0,%1,%2,%3}, {%4,%5,%6,%7}, {%8,%9}, {%0,%1,%2,%3};"
                       : "+f"(acc[mi][ni][0]), "+f"(acc[mi][ni][1]),
                         "+f"(acc[mi][ni][2]), "+f"(acc[mi][ni][3])
                       : "r"(af[cb][mi][0]), "r"(af[cb][mi][1]),
                         "r"(af[cb][mi][2]), "r"(af[cb][mi][3]),
                         "r"(bf[cb][ni][0]), "r"(bf[cb][ni][1]));
    }
  }

  // Epilogue (registers only)
  if (EPI == 3) {
    // interleaved [g|u] columns: even col = gate, odd col = up (same j)
    const long mb2 = m0 + wm * 64 + (lane >> 2);
    const int  jb  = ((n0 + wn * 64) >> 1) + (lane & 3);
    #pragma unroll
    for (int mi = 0; mi < 4; ++mi) {
      #pragma unroll
      for (int ni = 0; ni < 8; ++ni) {
        long r = mb2 + mi * 16;
        int  j = jb + ni * 4;
        float ga = acc[mi][ni][0], ua = acc[mi][ni][1];
        float gb2 = acc[mi][ni][2], ub = acc[mi][ni][3];
        float ha = ga / (1.f + __expf(-ga)) * ua;
        float hbv = gb2 / (1.f + __expf(-gb2)) * ub;
        OH[r * (long)Ndim + j]       = __float2half(ha);
        OH[(r + 8) * (long)Ndim + j] = __float2half(hbv);
      }
    }
    return;
  }
  const long mbase = m0 + wm * 64 + (lane >> 2);
  const long nbase = n0 + wn * 64 + (lane & 3) * 2;
  #pragma unroll
  for (int mi = 0; mi < 4; ++mi) {
    #pragma unroll
    for (int ni = 0; ni < 8; ++ni) {
      long r = mbase + mi * 16;
      long c = nbase + ni * 8;
      long i0 = r * Ndim + c;
      long i1 = (r + 8) * Ndim + c;
      float v0 = acc[mi][ni][0], v1 = acc[mi][ni][1];
      float v2 = acc[mi][ni][2], v3 = acc[mi][ni][3];
      if (EPI >= 1) {
        float2 ra = *(const float2*)(Rg + i0);
        float2 rb = *(const float2*)(Rg + i1);
        v0 += ra.x; v1 += ra.y; v2 += rb.x; v3 += rb.y;
        *(float2*)(OF + i0) = make_float2(v0, v1);
        *(float2*)(OF + i1) = make_float2(v2, v3);
      }
      if (EPI <= 1) {
        *(__half2*)(OH + i0) = __floats2half2_rn(v0, v1);
        *(__half2*)(OH + i1) = __floats2half2_rn(v2, v3);
      }
    }
  }
}

// ---------------------------------------------------------------------------
// Elementwise
// ---------------------------------------------------------------------------
__global__ void cvt_kernel(const float* __restrict__ x, __half* __restrict__ y) {
  long i = ((long)blockIdx.x * 256 + threadIdx.x) * 4;
  float4 v = *(const float4*)(x + i);
  __half2 lo = __floats2half2_rn(v.x, v.y);
  __half2 hi = __floats2half2_rn(v.z, v.w);
  uint2 pk;
  pk.x = *(uint32_t*)&lo;
  pk.y = *(uint32_t*)&hi;
  *(uint2*)(y + i) = pk;
}

// ---------------------------------------------------------------------------
// Host driver (graph-capturable; two streams forked/joined with events)
// ---------------------------------------------------------------------------
extern "C" void kernel_launch(void* const* d_in, const int* in_sizes, int n_in,
                              void* d_out, int out_size) {
  const float* x           = (const float*)d_in[0];
  const int*   codes_attn  = (const int*)  d_in[1];
  const float* scales_attn = (const float*)d_in[2];
  const int*   codes_gu    = (const int*)  d_in[3];
  const float* scales_gu   = (const float*)d_in[4];
  const int*   codes_down  = (const int*)  d_in[5];
  const float* scales_down = (const float*)d_in[6];
  const float* lora_A_h    = (const float*)d_in[7];
  const float* lora_A_down = (const float*)d_in[8];
  const float* lora_B_attn = (const float*)d_in[9];
  const float* lora_B_gu   = (const float*)d_in[10];
  const float* lora_B_down = (const float*)d_in[11];
  (void)in_sizes; (void)n_in; (void)out_size;

  __half *xh, *Wqkv, *Wo, *Wgu, *Wd, *attn, *x1h, *hb;
  float *x1f;
  cudaGetSymbolAddress((void**)&xh,   g_xh);
  cudaGetSymbolAddress((void**)&Wqkv, g_Wqkv);
  cudaGetSymbolAddress((void**)&Wo,   g_Wo);
  cudaGetSymbolAddress((void**)&Wgu,  g_Wgu);
  cudaGetSymbolAddress((void**)&Wd,   g_Wd);
  cudaGetSymbolAddress((void**)&attn, g_attn);
  cudaGetSymbolAddress((void**)&x1h,  g_x1h);
  cudaGetSymbolAddress((void**)&x1f,  g_x1f);
  cudaGetSymbolAddress((void**)&hb,   g_hb);

  cudaFuncSetAttribute(gemm_kernel<0>, cudaFuncAttributeMaxDynamicSharedMemorySize, SMEM_GEMM);
  cudaFuncSetAttribute(gemm_kernel<1>, cudaFuncAttributeMaxDynamicSharedMemorySize, SMEM_GEMM);
  cudaFuncSetAttribute(gemm_kernel<2>, cudaFuncAttributeMaxDynamicSharedMemorySize, SMEM_GEMM);
  cudaFuncSetAttribute(gemm_kernel<3>, cudaFuncAttributeMaxDynamicSharedMemorySize, SMEM_GEMM);

  // One-time side stream + events (created on first (correctness) call,
  // outside graph capture; reused deterministically every call).
  static cudaStream_t s1 = nullptr;
  static cudaEvent_t evFork = nullptr, evJoin = nullptr;
  if (s1 == nullptr) {
    cudaStreamCreateWithFlags(&s1, cudaStreamNonBlocking);
    cudaEventCreateWithFlags(&evFork, cudaEventDisableTiming);
    cudaEventCreateWithFlags(&evJoin, cudaEventDisableTiming);
  }

  // ---- fork: independent weight dequants on s1 -------------------------
  cudaEventRecord(evFork, 0);
  cudaStreamWaitEvent(s1, evFork, 0);

  dq1_kernel<<<dim3(HDIM / 1024, HDIM / 32), 256, 0, s1>>>(
      codes_attn + 3L * HDIM * HDIM, scales_attn + 3L * HDIM * (HDIM / 64),
      lora_A_h + 3L * RNK * HDIM, lora_B_attn + 3L * HDIM * RNK,
      Wo, HDIM, HDIM, HDIM);
  dq1_kernel<<<dim3(HDIM / 1024, IDIM / 32), 256, 0, s1>>>(
      codes_gu, scales_gu, lora_A_h + 4L * RNK * HDIM, lora_B_gu,
      Wgu, IDIM, HDIM, 2L * HDIM);                       // gate -> rows 2j
  dq1_kernel<<<dim3(HDIM / 1024, IDIM / 32), 256, 0, s1>>>(
      codes_gu + (long)IDIM * HDIM, scales_gu + (long)IDIM * (HDIM / 64),
      lora_A_h + 5L * RNK * HDIM, lora_B_gu + (long)IDIM * RNK,
      Wgu + HDIM, IDIM, HDIM, 2L * HDIM);                // up -> rows 2j+1
  dq1_kernel<<<dim3(IDIM / 1024, HDIM / 32), 256, 0, s1>>>(
      codes_down, scales_down, lora_A_down, lora_B_down,
      Wd, HDIM, IDIM, IDIM);
  cudaEventRecord(evJoin, s1);

  // ---- main stream: attn path ------------------------------------------
  cvt_kernel<<<(MDIM * (long)HDIM) / 1024, 256>>>(x, xh);
  dq3_kernel<<<dim3(HDIM / 512, HDIM / 32), 256>>>(
      codes_attn, scales_attn, lora_A_h, lora_B_attn, Wqkv, HDIM, HDIM,
      (long)HDIM * HDIM, (long)HDIM * (HDIM / 64), (long)HDIM * RNK, 1.f / 3.f);

  // attn = xh @ Wqkv^T   (already = (q+k+v)/3)
  gemm_kernel<0><<<dim3(MDIM / BM, HDIM / BN), 256, SMEM_GEMM>>>(
      xh, Wqkv, nullptr, attn, nullptr, HDIM, HDIM);

  // ---- join: all s1 dequants done before GEMM2 --------------------------
  cudaStreamWaitEvent(0, evJoin, 0);

  // x1 = x + attn @ Wo^T  (store fp32 + fp16)
  gemm_kernel<1><<<dim3(MDIM / BM, HDIM / BN), 256, SMEM_GEMM>>>(
      attn, Wo, x, x1h, x1f, HDIM, HDIM);
  // hb = silu(g) * u  fused into the gu GEMM (interleaved Wgu)
  gemm_kernel<3><<<dim3(MDIM / BM, (2 * IDIM) / BN), 256, SMEM_GEMM>>>(
      x1h, Wgu, nullptr, hb, nullptr, IDIM, HDIM);
  // out = x1 + hb @ Wd^T   (fp32 to d_out)
  gemm_kernel<2><<<dim3(MDIM / BM, HDIM / BN), 256, SMEM_GEMM>>>(
      hb, Wd, x1f, nullptr, (float*)d_out, HDIM, IDIM);
}

// round 16
// speedup vs baseline: 1.1036x; 1.0149x over previous
#include <cuda_runtime.h>
#include <cuda_fp16.h>
#include <cstdint>

// ---------------------------------------------------------------------------
// Problem dims (fixed by the dataset)
// ---------------------------------------------------------------------------
#define HDIM 4096
#define IDIM 14336
#define MDIM 4096   // BT * S = 2 * 2048
#define RNK  16

__constant__ float c_nf4[16] = {
  -1.0f, -0.6961928009986877f, -0.5250730514526367f, -0.39491748809814453f,
  -0.28444138169288635f, -0.18477343022823334f, -0.09105003625154495f, 0.0f,
  0.07958029955625534f, 0.16093020141124725f, 0.24611230194568634f,
  0.33791524171829224f, 0.44070982933044434f, 0.5626170039176941f,
  0.7229568362236023f, 1.0f};

// ---------------------------------------------------------------------------
// Scratch (static __device__ arrays: allocation-free per harness rules)
// ---------------------------------------------------------------------------
__device__ __half g_xh  [(size_t)MDIM * HDIM];
__device__ __half g_Wqkv[(size_t)HDIM * HDIM];
__device__ __half g_Wo  [(size_t)HDIM * HDIM];
__device__ __half g_Wgu [(size_t)2 * IDIM * HDIM];   // interleaved: row 2j=gate_j, 2j+1=up_j
__device__ __half g_Wd  [(size_t)HDIM * IDIM];
__device__ __half g_attn[(size_t)MDIM * HDIM];
__device__ __half g_x1h [(size_t)MDIM * HDIM];
__device__ float  g_x1f [(size_t)MDIM * HDIM];
__device__ __half g_hb  [(size_t)MDIM * IDIM];

// ---------------------------------------------------------------------------
// Dequant + LoRA-fold, QKV-fused (3 code planes summed, mul=1/3).
// 2 h per thread, rank-48 LoRA A in regs, depth-2 load rotation.
// ---------------------------------------------------------------------------
__global__ void __launch_bounds__(256, 1)
dq3_kernel(const int* __restrict__ codes,
           const float* __restrict__ scales,
           const float* __restrict__ Amat,   // [48, K]
           const float* __restrict__ Bmat,   // [4, O, 16] planes
           __half* __restrict__ W,
           int O, int K,
           long codePlane, long scalePlane, long bPlane,
           float mul)
{
  constexpr int RR = 48;
  constexpr int OT = 32;
  __shared__ float sB[OT * RR];
  const int tid = threadIdx.x;         // 256 threads
  const int h0 = blockIdx.x * 512;
  const int o0 = blockIdx.y * OT;

  for (int i = tid; i < OT * RR; i += 256) {
    int oi = i / RR, r = i - oi * RR;
    sB[i] = Bmat[(long)(r >> 4) * bPlane + (long)(o0 + oi) * RNK + (r & 15)];
  }
  const int h = h0 + tid * 2;
  float2 areg[RR];
  #pragma unroll
  for (int r = 0; r < RR; ++r) {
    areg[r].x = Amat[(long)r * K + h] * mul;
    areg[r].y = Amat[(long)r * K + h + 1] * mul;
  }
  __syncthreads();

  const int hb = h >> 6;
  const int ks6 = K >> 6;

  int2  cbuf[2][3];
  float sbuf[2][3];
  #pragma unroll
  for (int j = 0; j < 2; ++j)
    #pragma unroll
    for (int p = 0; p < 3; ++p) {
      cbuf[j][p] = *(const int2*)(codes + p * codePlane + (long)(o0 + j) * K + h);
      sbuf[j][p] = scales[p * scalePlane + (long)(o0 + j) * ks6 + hb];
    }

  #pragma unroll 2
  for (int oi = 0; oi < OT; ++oi) {
    const int slot = oi & 1;
    int2  cc[3];
    float ss[3];
    #pragma unroll
    for (int p = 0; p < 3; ++p) { cc[p] = cbuf[slot][p]; ss[p] = sbuf[slot][p]; }
    if (oi + 2 < OT) {
      #pragma unroll
      for (int p = 0; p < 3; ++p) {
        cbuf[slot][p] = *(const int2*)(codes + p * codePlane + (long)(o0 + oi + 2) * K + h);
        sbuf[slot][p] = scales[p * scalePlane + (long)(o0 + oi + 2) * ks6 + hb];
      }
    }
    float v0 = 0.f, v1 = 0.f;
    #pragma unroll
    for (int p = 0; p < 3; ++p) {
      v0 += c_nf4[cc[p].x & 15] * ss[p];
      v1 += c_nf4[cc[p].y & 15] * ss[p];
    }
    v0 *= mul; v1 *= mul;
    #pragma unroll
    for (int r = 0; r < RR; ++r) {
      float b = sB[oi * RR + r];
      v0 += b * areg[r].x;
      v1 += b * areg[r].y;
    }
    __half2 pk = __floats2half2_rn(v0, v1);
    *(__half2*)(W + (long)(o0 + oi) * K + h) = pk;
  }
}

// ---------------------------------------------------------------------------
// Dequant + LoRA-fold, single plane, 4 h per thread, 4-deep load rotation.
// rowStride (elements) allows interleaved output rows (gu fusion).
// ---------------------------------------------------------------------------
__global__ void dq1_kernel(const int* __restrict__ codes,
                           const float* __restrict__ scales,
                           const float* __restrict__ Amat,   // [16, K]
                           const float* __restrict__ Bmat,   // [O, 16]
                           __half* __restrict__ W,
                           int O, int K, long rowStride)
{
  constexpr int RR = 16;
  constexpr int OT = 32;
  __shared__ float sB[OT * RR];
  const int tid = threadIdx.x;         // 256 threads
  const int h0 = blockIdx.x * 1024;
  const int o0 = blockIdx.y * OT;

  for (int i = tid; i < OT * RR; i += 256) {
    int oi = i / RR, r = i - oi * RR;
    sB[i] = Bmat[(long)(o0 + oi) * RNK + r];
  }
  const int h = h0 + tid * 4;
  float4 areg[RR];
  #pragma unroll
  for (int r = 0; r < RR; ++r)
    areg[r] = *(const float4*)(Amat + (long)r * K + h);
  __syncthreads();

  const int hb = h >> 6;
  const int ks6 = K >> 6;

  int4  c[4];
  float s[4];
  #pragma unroll
  for (int j = 0; j < 4; ++j) {
    c[j] = *(const int4*)(codes + (long)(o0 + j) * K + h);
    s[j] = scales[(long)(o0 + j) * ks6 + hb];
  }

  #pragma unroll 4
  for (int oi = 0; oi < OT; ++oi) {
    const int slot = oi & 3;
    int4  cc = c[slot];
    float ss = s[slot];
    if (oi + 4 < OT) {
      c[slot] = *(const int4*)(codes + (long)(o0 + oi + 4) * K + h);
      s[slot] = scales[(long)(o0 + oi + 4) * ks6 + hb];
    }
    float v0 = c_nf4[cc.x & 15] * ss;
    float v1 = c_nf4[cc.y & 15] * ss;
    float v2 = c_nf4[cc.z & 15] * ss;
    float v3 = c_nf4[cc.w & 15] * ss;
    #pragma unroll
    for (int r = 0; r < RR; ++r) {
      float b = sB[oi * RR + r];
      v0 += b * areg[r].x;
      v1 += b * areg[r].y;
      v2 += b * areg[r].z;
      v3 += b * areg[r].w;
    }
    __half2 lo = __floats2half2_rn(v0, v1);
    __half2 hi = __floats2half2_rn(v2, v3);
    uint2 pk;
    pk.x = *(uint32_t*)&lo;
    pk.y = *(uint32_t*)&hi;
    *(uint2*)(W + (long)(o0 + oi) * rowStride + h) = pk;
  }
}

// ---------------------------------------------------------------------------
// fp16 GEMM:  C[M,N] = A[M,K] @ B[N,K]^T, fp32 accum.
// Tile 128x256x64, 8 warps (2x4), warp tile 64x64, mma.sync.m16n8k16.
// 4-stage cp.async pipeline; double-buffered LDSM frags; spread prefetch.
// EPI: 0 half(C); 1 f=resid+C f32+half; 2 f32 only; 3 silu(g)*u -> half (gu).
// ---------------------------------------------------------------------------
#define BM 128
#define BN 256
#define BK 64
#define STG 4
#define STAGE_B ((BM + BN) * BK * 2)          // 49152
#define SMEM_GEMM (STG * STAGE_B)             // 196608

__device__ __forceinline__ void cp16(uint32_t dst, const void* src) {
  asm volatile("cp.async.cg.shared.global [%0], [%1], 16;" :: "r"(dst), "l"(src));
}

__device__ __forceinline__ void gemm_load_stage(const __half* __restrict__ Ag,
                                                const __half* __restrict__ Bg,
                                                long Kdim, int m0, int n0,
                                                int lrow, int lcc, uint32_t off0,
                                                uint32_t sbase, int st, int kt)
{
  const long k0 = (long)kt * BK;
  uint32_t sA = sbase + (uint32_t)st * STAGE_B;
  uint32_t sB = sA + BM * BK * 2u;
  const __half* gA = Ag + (long)(m0 + lrow) * Kdim + k0 + lcc * 8;
  const __half* gB = Bg + (long)(n0 + lrow) * Kdim + k0 + lcc * 8;
  #pragma unroll
  for (int i = 0; i < 4; ++i)
    cp16(sA + off0 + (uint32_t)i * 4096u, gA + (long)i * 32 * Kdim);
  #pragma unroll
  for (int i = 0; i < 8; ++i)
    cp16(sB + off0 + (uint32_t)i * 4096u, gB + (long)i * 32 * Kdim);
  asm volatile("cp.async.commit_group;");
}

__device__ __forceinline__ void ld_frags(uint32_t sA, uint32_t sB,
                                         int wm, int wn, int lane, int ks,
                                         uint32_t af[4][4], uint32_t bf[8][2])
{
  #pragma unroll
  for (int mi = 0; mi < 4; ++mi) {
    int row = wm * 64 + mi * 16 + (lane & 15);
    int c3  = 2 * ks + (lane >> 4);
    uint32_t addr = sA + (uint32_t)row * 128u +
                    ((uint32_t)((c3 ^ (row & 7))) << 4);
    asm volatile("ldmatrix.sync.aligned.m8n8.x4.shared.b16 {%0,%1,%2,%3}, [%4];"
                 : "=r"(af[mi][0]), "=r"(af[mi][1]), "=r"(af[mi][2]), "=r"(af[mi][3])
                 : "r"(addr));
  }
  #pragma unroll
  for (int nb = 0; nb < 4; ++nb) {
    int row = wn * 64 + nb * 16 + (lane & 7) + ((lane >> 4) << 3);
    int c3  = 2 * ks + ((lane >> 3) & 1);
    uint32_t addr = sB + (uint32_t)row * 128u +
                    ((uint32_t)((c3 ^ (row & 7))) << 4);
    asm volatile("ldmatrix.sync.aligned.m8n8.x4.shared.b16 {%0,%1,%2,%3}, [%4];"
                 : "=r"(bf[2*nb][0]), "=r"(bf[2*nb][1]),
                   "=r"(bf[2*nb+1][0]), "=r"(bf[2*nb+1][1])
                 : "r"(addr));
  }
}

template<int EPI>
__global__ void __launch_bounds__(256, 1)
gemm_kernel(const __half* __restrict__ Ag, const __half* __restrict__ Bg,
            const float* __restrict__ Rg, __half* __restrict__ OH,
            float* __restrict__ OF, int Ndim, int Kdim)
{
  extern __shared__ __half smem[];
  const int tid  = threadIdx.x;
  const int m0   = blockIdx.x * BM;   // m fastest -> W n-band reused across wave
  const int n0   = blockIdx.y * BN;
  const uint32_t sbase = (uint32_t)__cvta_generic_to_shared(smem);
  const int warp = tid >> 5, lane = tid & 31;
  const int wm = warp & 1, wn = warp >> 1;          // 2 x 4 warps
  const int lrow = tid >> 3, lcc = tid & 7;
  const uint32_t off0 = (uint32_t)lrow * 128u +
                        ((uint32_t)(lcc ^ (lrow & 7)) << 4);
  const int KT = Kdim / BK;

  float acc[4][8][4];
  #pragma unroll
  for (int a = 0; a < 4; ++a)
    #pragma unroll
    for (int b = 0; b < 8; ++b)
      #pragma unroll
      for (int c = 0; c < 4; ++c) acc[a][b][c] = 0.f;

  gemm_load_stage(Ag, Bg, Kdim, m0, n0, lrow, lcc, off0, sbase, 0, 0);
  gemm_load_stage(Ag, Bg, Kdim, m0, n0, lrow, lcc, off0, sbase, 1, 1);
  gemm_load_stage(Ag, Bg, Kdim, m0, n0, lrow, lcc, off0, sbase, 2, 2);

  uint32_t af[2][4][4], bf[2][8][2];

  for (int kt = 0; kt < KT; ++kt) {
    asm volatile("cp.async.wait_group 2;");
    __syncthreads();

    uint32_t sA = sbase + (uint32_t)(kt & 3) * STAGE_B;
    uint32_t sB = sA + BM * BK * 2u;

    // Next-stage (kt+3); its buffer (kt-1)&3 was fully consumed in iter kt-1.
    const bool pf = (kt + 3 < KT);
    const long pk0 = (long)(kt + 3) * BK;
    uint32_t pA = sbase + (uint32_t)((kt + 3) & 3) * STAGE_B;
    uint32_t pB = pA + BM * BK * 2u;
    const __half* gA = Ag + (long)(m0 + lrow) * Kdim + pk0 + lcc * 8;
    const __half* gB = Bg + (long)(n0 + lrow) * Kdim + pk0 + lcc * 8;

    ld_frags(sA, sB, wm, wn, lane, 0, af[0], bf[0]);

    #pragma unroll
    for (int ks = 0; ks < 4; ++ks) {
      if (ks < 3)
        ld_frags(sA, sB, wm, wn, lane, ks + 1, af[(ks + 1) & 1], bf[(ks + 1) & 1]);
      if (ks == 0 && pf) {
        #pragma unroll
        for (int i = 0; i < 4; ++i)
          cp16(pA + off0 + (uint32_t)i * 4096u, gA + (long)i * 32 * Kdim);
      }
      if (ks == 1 && pf) {
        #pragma unroll
        for (int i = 0; i < 4; ++i)
          cp16(pB + off0 + (uint32_t)i * 4096u, gB + (long)i * 32 * Kdim);
      }
      if (ks == 2 && pf) {
        #pragma unroll
        for (int i = 4; i < 8; ++i)
          cp16(pB + off0 + (uint32_t)i * 4096u, gB + (long)i * 32 * Kdim);
      }
      if (ks == 3)
        asm volatile("cp.async.commit_group;");   // empty group at tail keeps count

      const int cb = ks & 1;
      #pragma unroll
      for (int mi = 0; mi < 4; ++mi)
        #pragma unroll
        for (int ni = 0; ni < 8; ++ni)
          asm volatile("mma.sync.aligned.m16n8k16.row.col.f32.f16.f16.f32 "
                       "{%0,%1,%2,%3}, {%4,%5,%6,%7}, {%8,%9}, {%0,%1,%2,%3};"
                       : "+f"(acc[mi][ni][0]), "+f"(acc[mi][ni][1]),
                         "+f"(acc[mi][ni][2]), "+f"(acc[mi][ni][3])
                       : "r"(af[cb][mi][0]), "r"(af[cb][mi][1]),
                         "r"(af[cb][mi][2]), "r"(af[cb][mi][3]),
                         "r"(bf[cb][ni][0]), "r"(bf[cb][ni][1]));
    }
  }

  // Epilogue (registers only)
  if (EPI == 3) {
    // interleaved [g|u] columns: even col = gate, odd col = up (same j)
    const long mb2 = m0 + wm * 64 + (lane >> 2);
    const int  jb  = ((n0 + wn * 64) >> 1) + (lane & 3);
    #pragma unroll
    for (int mi = 0; mi < 4; ++mi) {
      #pragma unroll
      for (int ni = 0; ni < 8; ++ni) {
        long r = mb2 + mi * 16;
        int  j = jb + ni * 4;
        float ga = acc[mi][ni][0], ua = acc[mi][ni][1];
        float gb2 = acc[mi][ni][2], ub = acc[mi][ni][3];
        float ha = ga / (1.f + __expf(-ga)) * ua;
        float hbv = gb2 / (1.f + __expf(-gb2)) * ub;
        OH[r * (long)Ndim + j]       = __float2half(ha);
        OH[(r + 8) * (long)Ndim + j] = __float2half(hbv);
      }
    }
    return;
  }
  const long mbase = m0 + wm * 64 + (lane >> 2);
  const long nbase = n0 + wn * 64 + (lane & 3) * 2;
  #pragma unroll
  for (int mi = 0; mi < 4; ++mi) {
    #pragma unroll
    for (int ni = 0; ni < 8; ++ni) {
      long r = mbase + mi * 16;
      long c = nbase + ni * 8;
      long i0 = r * Ndim + c;
      long i1 = (r + 8) * Ndim + c;
      float v0 = acc[mi][ni][0], v1 = acc[mi][ni][1];
      float v2 = acc[mi][ni][2], v3 = acc[mi][ni][3];
      if (EPI >= 1) {
        float2 ra = *(const float2*)(Rg + i0);
        float2 rb = *(const float2*)(Rg + i1);
        v0 += ra.x; v1 += ra.y; v2 += rb.x; v3 += rb.y;
        *(float2*)(OF + i0) = make_float2(v0, v1);
        *(float2*)(OF + i1) = make_float2(v2, v3);
      }
      if (EPI <= 1) {
        *(__half2*)(OH + i0) = __floats2half2_rn(v0, v1);
        *(__half2*)(OH + i1) = __floats2half2_rn(v2, v3);
      }
    }
  }
}

// ---------------------------------------------------------------------------
// Elementwise
// ---------------------------------------------------------------------------
__global__ void cvt_kernel(const float* __restrict__ x, __half* __restrict__ y) {
  long i = ((long)blockIdx.x * 256 + threadIdx.x) * 4;
  float4 v = *(const float4*)(x + i);
  __half2 lo = __floats2half2_rn(v.x, v.y);
  __half2 hi = __floats2half2_rn(v.z, v.w);
  uint2 pk;
  pk.x = *(uint32_t*)&lo;
  pk.y = *(uint32_t*)&hi;
  *(uint2*)(y + i) = pk;
}

// ---------------------------------------------------------------------------
// Host driver (graph-capturable; per-weight events so no dequant ever gates
// the GEMM chain later than necessary)
// ---------------------------------------------------------------------------
extern "C" void kernel_launch(void* const* d_in, const int* in_sizes, int n_in,
                              void* d_out, int out_size) {
  const float* x           = (const float*)d_in[0];
  const int*   codes_attn  = (const int*)  d_in[1];
  const float* scales_attn = (const float*)d_in[2];
  const int*   codes_gu    = (const int*)  d_in[3];
  const float* scales_gu   = (const float*)d_in[4];
  const int*   codes_down  = (const int*)  d_in[5];
  const float* scales_down = (const float*)d_in[6];
  const float* lora_A_h    = (const float*)d_in[7];
  const float* lora_A_down = (const float*)d_in[8];
  const float* lora_B_attn = (const float*)d_in[9];
  const float* lora_B_gu   = (const float*)d_in[10];
  const float* lora_B_down = (const float*)d_in[11];
  (void)in_sizes; (void)n_in; (void)out_size;

  __half *xh, *Wqkv, *Wo, *Wgu, *Wd, *attn, *x1h, *hb;
  float *x1f;
  cudaGetSymbolAddress((void**)&xh,   g_xh);
  cudaGetSymbolAddress((void**)&Wqkv, g_Wqkv);
  cudaGetSymbolAddress((void**)&Wo,   g_Wo);
  cudaGetSymbolAddress((void**)&Wgu,  g_Wgu);
  cudaGetSymbolAddress((void**)&Wd,   g_Wd);
  cudaGetSymbolAddress((void**)&attn, g_attn);
  cudaGetSymbolAddress((void**)&x1h,  g_x1h);
  cudaGetSymbolAddress((void**)&x1f,  g_x1f);
  cudaGetSymbolAddress((void**)&hb,   g_hb);

  cudaFuncSetAttribute(gemm_kernel<0>, cudaFuncAttributeMaxDynamicSharedMemorySize, SMEM_GEMM);
  cudaFuncSetAttribute(gemm_kernel<1>, cudaFuncAttributeMaxDynamicSharedMemorySize, SMEM_GEMM);
  cudaFuncSetAttribute(gemm_kernel<2>, cudaFuncAttributeMaxDynamicSharedMemorySize, SMEM_GEMM);
  cudaFuncSetAttribute(gemm_kernel<3>, cudaFuncAttributeMaxDynamicSharedMemorySize, SMEM_GEMM);

  // One-time side streams + events (created on first (correctness) call,
  // outside graph capture; reused deterministically every call).
  static cudaStream_t s1 = nullptr, s2 = nullptr;
  static cudaEvent_t evFork = nullptr, evDq3 = nullptr,
                     evWo = nullptr, evWgu = nullptr, evWd = nullptr;
  if (s1 == nullptr) {
    cudaStreamCreateWithFlags(&s1, cudaStreamNonBlocking);
    cudaStreamCreateWithFlags(&s2, cudaStreamNonBlocking);
    cudaEventCreateWithFlags(&evFork, cudaEventDisableTiming);
    cudaEventCreateWithFlags(&evDq3,  cudaEventDisableTiming);
    cudaEventCreateWithFlags(&evWo,   cudaEventDisableTiming);
    cudaEventCreateWithFlags(&evWgu,  cudaEventDisableTiming);
    cudaEventCreateWithFlags(&evWd,   cudaEventDisableTiming);
  }

  // ---- fork ------------------------------------------------------------
  cudaEventRecord(evFork, 0);
  cudaStreamWaitEvent(s1, evFork, 0);
  cudaStreamWaitEvent(s2, evFork, 0);

  // s2: qkv-fused dequant, concurrent with cvt on main (gates G1 only)
  dq3_kernel<<<dim3(HDIM / 512, HDIM / 32), 256, 0, s2>>>(
      codes_attn, scales_attn, lora_A_h, lora_B_attn, Wqkv, HDIM, HDIM,
      (long)HDIM * HDIM, (long)HDIM * (HDIM / 64), (long)HDIM * RNK, 1.f / 3.f);
  cudaEventRecord(evDq3, s2);

  // s1: remaining dequants in consumer order, one event per weight
  dq1_kernel<<<dim3(HDIM / 1024, HDIM / 32), 256, 0, s1>>>(
      codes_attn + 3L * HDIM * HDIM, scales_attn + 3L * HDIM * (HDIM / 64),
      lora_A_h + 3L * RNK * HDIM, lora_B_attn + 3L * HDIM * RNK,
      Wo, HDIM, HDIM, HDIM);
  cudaEventRecord(evWo, s1);
  dq1_kernel<<<dim3(HDIM / 1024, IDIM / 32), 256, 0, s1>>>(
      codes_gu, scales_gu, lora_A_h + 4L * RNK * HDIM, lora_B_gu,
      Wgu, IDIM, HDIM, 2L * HDIM);                       // gate -> rows 2j
  dq1_kernel<<<dim3(HDIM / 1024, IDIM / 32), 256, 0, s1>>>(
      codes_gu + (long)IDIM * HDIM, scales_gu + (long)IDIM * (HDIM / 64),
      lora_A_h + 5L * RNK * HDIM, lora_B_gu + (long)IDIM * RNK,
      Wgu + HDIM, IDIM, HDIM, 2L * HDIM);                // up -> rows 2j+1
  cudaEventRecord(evWgu, s1);
  dq1_kernel<<<dim3(IDIM / 1024, HDIM / 32), 256, 0, s1>>>(
      codes_down, scales_down, lora_A_down, lora_B_down,
      Wd, HDIM, IDIM, IDIM);
  cudaEventRecord(evWd, s1);

  // ---- main stream: x -> fp16, then GEMM chain -------------------------
  cvt_kernel<<<(MDIM * (long)HDIM) / 1024, 256>>>(x, xh);

  cudaStreamWaitEvent(0, evDq3, 0);
  // attn = xh @ Wqkv^T   (already = (q+k+v)/3)
  gemm_kernel<0><<<dim3(MDIM / BM, HDIM / BN), 256, SMEM_GEMM>>>(
      xh, Wqkv, nullptr, attn, nullptr, HDIM, HDIM);

  cudaStreamWaitEvent(0, evWo, 0);
  // x1 = x + attn @ Wo^T  (store fp32 + fp16)
  gemm_kernel<1><<<dim3(MDIM / BM, HDIM / BN), 256, SMEM_GEMM>>>(
      attn, Wo, x, x1h, x1f, HDIM, HDIM);

  cudaStreamWaitEvent(0, evWgu, 0);
  // hb = silu(g) * u  fused into the gu GEMM (interleaved Wgu)
  gemm_kernel<3><<<dim3(MDIM / BM, (2 * IDIM) / BN), 256, SMEM_GEMM>>>(
      x1h, Wgu, nullptr, hb, nullptr, IDIM, HDIM);

  cudaStreamWaitEvent(0, evWd, 0);
  // out = x1 + hb @ Wd^T   (fp32 to d_out)
  gemm_kernel<2><<<dim3(MDIM / BM, HDIM / BN), 256, SMEM_GEMM>>>(
      hb, Wd, x1f, nullptr, (float*)d_out, HDIM, IDIM);
}